// round 2
// baseline (speedup 1.0000x reference)
#include <cuda_runtime.h>
#include <math.h>
#include <float.h>

#define NN 50000
#define NE 800000
#define NHEAD 4

// ---------------- scratch (device globals; no allocation allowed) ----------------
__device__ float g_z[(size_t)NN * 1024];   // projected feats of current layer (max H*F = 1024)
__device__ float g_h[(size_t)NN * 256];    // hidden activations between layers
__device__ float g_el[NN * NHEAD];
__device__ float g_er[NN * NHEAD];
__device__ float g_es[(size_t)NE * NHEAD];     // edge scores, dst-sorted order
__device__ float g_alpha[(size_t)NE * NHEAD];  // normalized attention, dst-sorted order
__device__ int   g_ss[NE];                     // src node per sorted edge
__device__ int   g_eidx[NE];                   // sorted-pos -> original edge id
__device__ int   g_deg[NN];
__device__ int   g_cur[NN];
__device__ int   g_off[NN + 1];

// ---------------- CSR build (by destination) ----------------
__global__ void k_zero_deg() {
    int i = blockIdx.x * blockDim.x + threadIdx.x;
    if (i < NN) g_deg[i] = 0;
}

__global__ void k_count(const int* __restrict__ dst) {
    int i = blockIdx.x * blockDim.x + threadIdx.x;
    if (i < NE) atomicAdd(&g_deg[dst[i]], 1);
}

__global__ void k_scan() {
    __shared__ int sh[1024];
    __shared__ int carry;
    if (threadIdx.x == 0) carry = 0;
    __syncthreads();
    for (int base = 0; base < NN; base += 1024) {
        int i = base + threadIdx.x;
        int v = (i < NN) ? g_deg[i] : 0;
        sh[threadIdx.x] = v;
        __syncthreads();
        for (int o = 1; o < 1024; o <<= 1) {
            int t = (threadIdx.x >= o) ? sh[threadIdx.x - o] : 0;
            __syncthreads();
            sh[threadIdx.x] += t;
            __syncthreads();
        }
        if (i < NN) {
            int excl = carry + sh[threadIdx.x] - v;
            g_off[i] = excl;
            g_cur[i] = excl;
        }
        __syncthreads();
        if (threadIdx.x == 0) carry += sh[1023];
        __syncthreads();
    }
    if (threadIdx.x == 0) g_off[NN] = carry;
}

__global__ void k_fill(const int* __restrict__ dst) {
    int i = blockIdx.x * blockDim.x + threadIdx.x;
    if (i < NE) {
        int d = dst[i];
        int p = atomicAdd(&g_cur[d], 1);
        g_eidx[p] = i;
    }
}

// ---------------- SGEMM: C[M,N] = A[M,K] @ B[K,N], fp32, row-major ----------------
// BM=BN=128, BK=8, 256 threads, 8x8 micro-tile. N, K assumed multiples of 128/8; M guarded.
__global__ void __launch_bounds__(256) k_sgemm(const float* __restrict__ A,
                                               const float* __restrict__ B,
                                               float* __restrict__ C,
                                               int M, int N, int K) {
    const int BM = 128, BN = 128, BK = 8;
    __shared__ float As[BK][BM];
    __shared__ float Bs[BK][BN];
    int bm = blockIdx.y * BM, bn = blockIdx.x * BN;
    int tid = threadIdx.x;
    int arow = tid >> 1;
    int acol = (tid & 1) * 4;
    int brow = tid >> 5;
    int bcol = (tid & 31) * 4;
    int ty = tid >> 4, tx = tid & 15;
    float acc[8][8];
#pragma unroll
    for (int i = 0; i < 8; i++)
#pragma unroll
        for (int j = 0; j < 8; j++) acc[i][j] = 0.f;

    for (int k0 = 0; k0 < K; k0 += BK) {
        float4 av = make_float4(0.f, 0.f, 0.f, 0.f);
        int gm = bm + arow;
        if (gm < M)
            av = *reinterpret_cast<const float4*>(&A[(size_t)gm * K + k0 + acol]);
        As[acol + 0][arow] = av.x;
        As[acol + 1][arow] = av.y;
        As[acol + 2][arow] = av.z;
        As[acol + 3][arow] = av.w;
        *reinterpret_cast<float4*>(&Bs[brow][bcol]) =
            *reinterpret_cast<const float4*>(&B[(size_t)(k0 + brow) * N + bn + bcol]);
        __syncthreads();
#pragma unroll
        for (int k = 0; k < BK; k++) {
            float ra[8], rb[8];
#pragma unroll
            for (int i = 0; i < 8; i++) ra[i] = As[k][ty * 8 + i];
#pragma unroll
            for (int j = 0; j < 8; j++) rb[j] = Bs[k][tx * 8 + j];
#pragma unroll
            for (int i = 0; i < 8; i++)
#pragma unroll
                for (int j = 0; j < 8; j++) acc[i][j] += ra[i] * rb[j];
        }
        __syncthreads();
    }
#pragma unroll
    for (int i = 0; i < 8; i++) {
        int gm = bm + ty * 8 + i;
        if (gm < M) {
#pragma unroll
            for (int j = 0; j < 8; j += 4) {
                float4 v = make_float4(acc[i][j], acc[i][j + 1], acc[i][j + 2], acc[i][j + 3]);
                *reinterpret_cast<float4*>(&C[(size_t)gm * N + bn + tx * 8 + j]) = v;
            }
        }
    }
}

// ---------------- per-node attention scores el/er ----------------
template <int F>
__global__ void k_scores(const float* __restrict__ z, const float* __restrict__ al,
                         const float* __restrict__ ar) {
    int gw = (blockIdx.x * blockDim.x + threadIdx.x) >> 5;
    int lane = threadIdx.x & 31;
    if (gw >= NN) return;
    const float* row = z + (size_t)gw * (NHEAD * F);
    const int PERH = F / 32;
    float accl[NHEAD], accr[NHEAD];
#pragma unroll
    for (int h = 0; h < NHEAD; h++) { accl[h] = 0.f; accr[h] = 0.f; }
#pragma unroll
    for (int i = 0; i < NHEAD * PERH; i++) {
        int j = lane + 32 * i;
        float v = row[j];
        int h = i / PERH;   // lane-independent: head per 32-chunk group
        accl[h] += v * al[j];
        accr[h] += v * ar[j];
    }
#pragma unroll
    for (int h = 0; h < NHEAD; h++) {
        float l = accl[h], r = accr[h];
#pragma unroll
        for (int o = 16; o > 0; o >>= 1) {
            l += __shfl_xor_sync(0xffffffffu, l, o);
            r += __shfl_xor_sync(0xffffffffu, r, o);
        }
        if (lane == 0) {
            g_el[gw * NHEAD + h] = l;
            g_er[gw * NHEAD + h] = r;
        }
    }
}

// ---------------- edge scores in dst-sorted order ----------------
__global__ void k_edge(const int* __restrict__ src, const int* __restrict__ dst) {
    int j = blockIdx.x * blockDim.x + threadIdx.x;
    if (j >= NE) return;
    int e = g_eidx[j];
    int s = src[e], d = dst[e];
    float4 l = *reinterpret_cast<const float4*>(&g_el[s * 4]);
    float4 r = *reinterpret_cast<const float4*>(&g_er[d * 4]);
    float4 v;
    float x;
    x = l.x + r.x; v.x = x > 0.f ? x : 0.2f * x;
    x = l.y + r.y; v.y = x > 0.f ? x : 0.2f * x;
    x = l.z + r.z; v.z = x > 0.f ? x : 0.2f * x;
    x = l.w + r.w; v.w = x > 0.f ? x : 0.2f * x;
    *reinterpret_cast<float4*>(&g_es[(size_t)j * 4]) = v;
    g_ss[j] = s;
}

// ---------------- per-node segment softmax: write alpha ----------------
__global__ void k_stats() {
    int n = (blockIdx.x * blockDim.x + threadIdx.x) >> 5;
    int lane = threadIdx.x & 31;
    if (n >= NN) return;
    int j0 = g_off[n], j1 = g_off[n + 1];
    float m[NHEAD], s[NHEAD];
#pragma unroll
    for (int h = 0; h < NHEAD; h++) { m[h] = -FLT_MAX; s[h] = 0.f; }
    for (int j = j0 + lane; j < j1; j += 32) {
        float4 e4 = *reinterpret_cast<const float4*>(&g_es[(size_t)j * 4]);
        float ev[4] = {e4.x, e4.y, e4.z, e4.w};
#pragma unroll
        for (int h = 0; h < NHEAD; h++) {
            float nm = fmaxf(m[h], ev[h]);
            s[h] = s[h] * __expf(m[h] - nm) + __expf(ev[h] - nm);
            m[h] = nm;
        }
    }
#pragma unroll
    for (int h = 0; h < NHEAD; h++) {
#pragma unroll
        for (int o = 16; o > 0; o >>= 1) {
            float om = __shfl_xor_sync(0xffffffffu, m[h], o);
            float os = __shfl_xor_sync(0xffffffffu, s[h], o);
            float nm = fmaxf(m[h], om);
            s[h] = s[h] * __expf(m[h] - nm) + os * __expf(om - nm);
            m[h] = nm;
        }
    }
    float inv[NHEAD];
#pragma unroll
    for (int h = 0; h < NHEAD; h++) inv[h] = 1.f / fmaxf(s[h], 1e-9f);
    for (int j = j0 + lane; j < j1; j += 32) {
        float4 e4 = *reinterpret_cast<const float4*>(&g_es[(size_t)j * 4]);
        float4 a;
        a.x = __expf(e4.x - m[0]) * inv[0];
        a.y = __expf(e4.y - m[1]) * inv[1];
        a.z = __expf(e4.z - m[2]) * inv[2];
        a.w = __expf(e4.w - m[3]) * inv[3];
        *reinterpret_cast<float4*>(&g_alpha[(size_t)j * 4]) = a;
    }
}

// ---------------- aggregation for hidden layers (F=64, ELU, +bias) ----------------
__global__ void k_agg_mid(const float* __restrict__ z, const float* __restrict__ bias,
                          float* __restrict__ hout) {
    int gw = (blockIdx.x * blockDim.x + threadIdx.x) >> 5;
    int lane = threadIdx.x & 31;
    if (gw >= NN * NHEAD) return;
    int n = gw >> 2, h = gw & 3;
    int j0 = g_off[n], j1 = g_off[n + 1];
    float a0 = 0.f, a1 = 0.f;
    for (int j = j0; j < j1; j++) {
        float a = g_alpha[(size_t)j * 4 + h];
        const float* zr = z + (size_t)g_ss[j] * 256 + h * 64;
        a0 += a * zr[lane];
        a1 += a * zr[lane + 32];
    }
    float v0 = a0 + bias[h * 64 + lane];
    float v1 = a1 + bias[h * 64 + lane + 32];
    v0 = v0 > 0.f ? v0 : (__expf(v0) - 1.f);
    v1 = v1 > 0.f ? v1 : (__expf(v1) - 1.f);
    hout[(size_t)n * 256 + h * 64 + lane] = v0;
    hout[(size_t)n * 256 + h * 64 + lane + 32] = v1;
}

// ---------------- final aggregation (F=256, +bias, mean over heads) ----------------
__global__ void k_agg_final(const float* __restrict__ z, const float* __restrict__ b2,
                            float* __restrict__ out) {
    int n = (blockIdx.x * blockDim.x + threadIdx.x) >> 5;
    int lane = threadIdx.x & 31;
    if (n >= NN) return;
    int j0 = g_off[n], j1 = g_off[n + 1];
    float acc[8];
#pragma unroll
    for (int p = 0; p < 8; p++) acc[p] = 0.f;
    for (int j = j0; j < j1; j++) {
        float4 a = *reinterpret_cast<const float4*>(&g_alpha[(size_t)j * 4]);
        const float* zr = z + (size_t)g_ss[j] * 1024;
#pragma unroll
        for (int p = 0; p < 8; p++) {
            int c = lane + 32 * p;
            acc[p] += a.x * zr[c] + a.y * zr[256 + c] + a.z * zr[512 + c] + a.w * zr[768 + c];
        }
    }
#pragma unroll
    for (int p = 0; p < 8; p++) {
        int c = lane + 32 * p;
        float bs = b2[c] + b2[256 + c] + b2[512 + c] + b2[768 + c];
        out[(size_t)n * 256 + c] = 0.25f * (acc[p] + bs);
    }
}

// ---------------- launch ----------------
extern "C" void kernel_launch(void* const* d_in, const int* in_sizes, int n_in,
                              void* d_out, int out_size) {
    const float* feat = (const float*)d_in[0];
    const float* W0 = (const float*)d_in[1];
    const float* al0 = (const float*)d_in[2];
    const float* ar0 = (const float*)d_in[3];
    const float* b0 = (const float*)d_in[4];
    const float* W1 = (const float*)d_in[5];
    const float* al1 = (const float*)d_in[6];
    const float* ar1 = (const float*)d_in[7];
    const float* b1 = (const float*)d_in[8];
    const float* W2 = (const float*)d_in[9];
    const float* al2 = (const float*)d_in[10];
    const float* ar2 = (const float*)d_in[11];
    const float* b2 = (const float*)d_in[12];
    const int* src = (const int*)d_in[13];
    const int* dst = (const int*)d_in[14];
    float* out = (float*)d_out;

    float *p_z = nullptr, *p_h = nullptr;
    cudaGetSymbolAddress((void**)&p_z, g_z);
    cudaGetSymbolAddress((void**)&p_h, g_h);

    const int TB = 256;
    int eb = (NE + TB - 1) / TB;
    int nwb = (NN * 32 + TB - 1) / TB;       // one warp per node
    int nhwb = (NN * NHEAD * 32 + TB - 1) / TB;  // one warp per (node, head)

    // CSR build (per-launch, deterministic work)
    k_zero_deg<<<(NN + TB - 1) / TB, TB>>>();
    k_count<<<eb, TB>>>(dst);
    k_scan<<<1, 1024>>>();
    k_fill<<<eb, TB>>>(dst);

    // ---- layer 0: 128 -> 4x64, ELU
    k_sgemm<<<dim3(256 / 128, (NN + 127) / 128), 256>>>(feat, W0, p_z, NN, 256, 128);
    k_scores<64><<<nwb, TB>>>(p_z, al0, ar0);
    k_edge<<<eb, TB>>>(src, dst);
    k_stats<<<nwb, TB>>>();
    k_agg_mid<<<nhwb, TB>>>(p_z, b0, p_h);

    // ---- layer 1: 256 -> 4x64, ELU
    k_sgemm<<<dim3(256 / 128, (NN + 127) / 128), 256>>>(p_h, W1, p_z, NN, 256, 256);
    k_scores<64><<<nwb, TB>>>(p_z, al1, ar1);
    k_edge<<<eb, TB>>>(src, dst);
    k_stats<<<nwb, TB>>>();
    k_agg_mid<<<nhwb, TB>>>(p_z, b1, p_h);

    // ---- layer 2: 256 -> 4x256, mean over heads
    k_sgemm<<<dim3(1024 / 128, (NN + 127) / 128), 256>>>(p_h, W2, p_z, NN, 1024, 256);
    k_scores<256><<<nwb, TB>>>(p_z, al2, ar2);
    k_edge<<<eb, TB>>>(src, dst);
    k_stats<<<nwb, TB>>>();
    k_agg_final<<<nwb, TB>>>(p_z, b2, out);
}